// round 8
// baseline (speedup 1.0000x reference)
#include <cuda_runtime.h>
#include <cstdint>

#define D 64
#define NMAX 100000
#define EMAX 1664000

// ---------------------------------------------------------------------------
// Device scratch
// ---------------------------------------------------------------------------
__device__ float4  g_hnew4[NMAX * (D / 4)];   // h_new result (25.6 MB)
__device__ uint2   g_rec[EMAX];               // CSR records: (src, w bits)
__device__ int     g_cnt[NMAX];               // histogram / write cursors
__device__ int     g_off[NMAX + 1];           // CSR row offsets
__device__ uint8_t g_Bimg[139264];            // bf16 hi+lo weight image
__device__ float   g_biasf[256];              // fused biases, col' = j*4+gate
__device__ int     g_is32;                    // src/dst dtype flag

// SMEM map for the GEMM kernel
#define STRIDE_A 272            // 128 k * 2B padded to 17*16B (ldmatrix conflict-free)
#define A_HALF_W 4352           // per-warp A half: 16 rows * 272
#define A_WARP   8704           // per-warp A region (hi + lo)
#define B_HALF   69632          // 256 rows * 272
#define SM_BIAS  0
#define SM_A     1024
#define SM_B     (SM_A + 8 * A_WARP)          // 70656
#define SM_TOT   (SM_B + 2 * B_HALF)          // 209920

// ---------------------------------------------------------------------------
// Helpers
// ---------------------------------------------------------------------------
__device__ __forceinline__ uint32_t smem_u32(const void* p) {
    uint32_t a;
    asm("{ .reg .u64 t; cvta.to.shared.u64 t, %1; cvt.u32.u64 %0, t; }"
        : "=r"(a) : "l"(p));
    return a;
}
__device__ __forceinline__ uint32_t cvtbf2(float hi, float lo) {
    uint32_t d;
    asm("cvt.rn.bf16x2.f32 %0, %1, %2;" : "=r"(d) : "f"(hi), "f"(lo));
    return d;
}
__device__ __forceinline__ float bflo_f(uint32_t p) { return __uint_as_float(p << 16); }
__device__ __forceinline__ float bfhi_f(uint32_t p) { return __uint_as_float(p & 0xffff0000u); }

__device__ __forceinline__ float sigmoidf_fast(float x) {
    return __fdividef(1.0f, 1.0f + __expf(-x));
}
__device__ __forceinline__ float tanhf_fast(float x) {
    return 1.0f - __fdividef(2.0f, __expf(2.0f * x) + 1.0f);
}

#define LDSM4(r0, r1, r2, r3, a)                                            \
    asm volatile("ldmatrix.sync.aligned.m8n8.x4.shared.b16 {%0,%1,%2,%3}, [%4];" \
                 : "=r"(r0), "=r"(r1), "=r"(r2), "=r"(r3) : "r"(a))

#define MMA16816(c, a0, a1, a2, a3, b0, b1)                                 \
    asm volatile("mma.sync.aligned.m16n8k16.row.col.f32.bf16.bf16.f32 "     \
                 "{%0,%1,%2,%3}, {%4,%5,%6,%7}, {%8,%9}, {%0,%1,%2,%3};"    \
                 : "+f"((c)[0]), "+f"((c)[1]), "+f"((c)[2]), "+f"((c)[3])   \
                 : "r"(a0), "r"(a1), "r"(a2), "r"(a3), "r"(b0), "r"(b1))

// ---------------------------------------------------------------------------
// Kernel 0: index dtype detection (int32 vs int64 node ids)
// ---------------------------------------------------------------------------
__global__ void detect_kernel(const unsigned long long* __restrict__ src,
                              const unsigned long long* __restrict__ dst) {
    if (threadIdx.x == 0 && blockIdx.x == 0) {
        unsigned long long acc = 0;
#pragma unroll
        for (int i = 0; i < 8; i++) acc |= (src[i] >> 32) | (dst[i] >> 32);
        g_is32 = (acc != 0ULL) ? 1 : 0;
    }
}

// ---------------------------------------------------------------------------
// CSR build: zero counts -> histogram(dst) -> prefix scan -> reorder records
// ---------------------------------------------------------------------------
__global__ void zcnt_kernel(int Nn) {
    int i = blockIdx.x * blockDim.x + threadIdx.x;
    if (i < Nn) g_cnt[i] = 0;
}

__global__ void hist_kernel(const void* __restrict__ dstp, int E) {
    int e = blockIdx.x * blockDim.x + threadIdx.x;
    if (e >= E) return;
    int d = g_is32 ? ((const int*)dstp)[e]
                   : (int)((const long long*)dstp)[e];
    atomicAdd(&g_cnt[d], 1);
}

// Single-CTA (1024 thr) exclusive scan over Nn counts. Writes g_off and
// resets g_cnt[i] to the start offset (reorder cursor).
__global__ void __launch_bounds__(1024) scan_kernel(int Nn, int E) {
    __shared__ int wsums[32];
    const int tid = threadIdx.x, lane = tid & 31, wid = tid >> 5;
    const int chunk = (Nn + 1023) >> 10;
    const int b0 = tid * chunk;
    const int b1 = min(b0 + chunk, Nn);

    int s = 0;
    for (int i = b0; i < b1; i++) s += g_cnt[i];

    int v = s;
#pragma unroll
    for (int d = 1; d < 32; d <<= 1) {
        int n = __shfl_up_sync(0xffffffffu, v, d);
        if (lane >= d) v += n;
    }
    if (lane == 31) wsums[wid] = v;
    __syncthreads();
    if (wid == 0) {
        int wv = wsums[lane];
#pragma unroll
        for (int d = 1; d < 32; d <<= 1) {
            int n = __shfl_up_sync(0xffffffffu, wv, d);
            if (lane >= d) wv += n;
        }
        wsums[lane] = wv;
    }
    __syncthreads();

    int run = (wid ? wsums[wid - 1] : 0) + v - s;   // exclusive prefix
    for (int i = b0; i < b1; i++) {
        int c = g_cnt[i];
        g_off[i] = run;
        g_cnt[i] = run;                              // cursor for reorder
        run += c;
    }
    if (tid == 1023) g_off[Nn] = E;
}

__global__ void reorder_kernel(const void* __restrict__ srcp,
                               const void* __restrict__ dstp,
                               const float* __restrict__ ew, int E) {
    int e = blockIdx.x * blockDim.x + threadIdx.x;
    if (e >= E) return;
    int s, d;
    if (g_is32) {
        s = ((const int*)srcp)[e];
        d = ((const int*)dstp)[e];
    } else {
        s = (int)((const long long*)srcp)[e];
        d = (int)((const long long*)dstp)[e];
    }
    int pos = atomicAdd(&g_cnt[d], 1);
    g_rec[pos] = make_uint2((uint32_t)s, __float_as_uint(__ldg(&ew[e])));
}

// ---------------------------------------------------------------------------
// Accumulate: half-warp (16 lanes) per node; lane owns one float4 part of the
// 256B row. Registers accumulate over the node's CSR records; ONE plain store
// per row — no atomics, no zero pass. 2-edge unroll for MLP.
// ---------------------------------------------------------------------------
__global__ void __launch_bounds__(256) accum_kernel(const float4* __restrict__ h4,
                                                    int Nn) {
    int gid = blockIdx.x * blockDim.x + threadIdx.x;
    int node = gid >> 4, p = gid & 15;
    if (node >= Nn) return;
    int e = g_off[node];
    const int end = g_off[node + 1];
    float4 acc = make_float4(0.f, 0.f, 0.f, 0.f);

    for (; e + 2 <= end; e += 2) {
        uint2 r0 = g_rec[e], r1 = g_rec[e + 1];
        float4 v0 = __ldg(&h4[(size_t)r0.x * 16 + p]);
        float4 v1 = __ldg(&h4[(size_t)r1.x * 16 + p]);
        float w0 = __uint_as_float(r0.y), w1 = __uint_as_float(r1.y);
        acc.x = fmaf(v0.x, w0, acc.x); acc.y = fmaf(v0.y, w0, acc.y);
        acc.z = fmaf(v0.z, w0, acc.z); acc.w = fmaf(v0.w, w0, acc.w);
        acc.x = fmaf(v1.x, w1, acc.x); acc.y = fmaf(v1.y, w1, acc.y);
        acc.z = fmaf(v1.z, w1, acc.z); acc.w = fmaf(v1.w, w1, acc.w);
    }
    if (e < end) {
        uint2 r = g_rec[e];
        float4 v = __ldg(&h4[(size_t)r.x * 16 + p]);
        float w = __uint_as_float(r.y);
        acc.x = fmaf(v.x, w, acc.x); acc.y = fmaf(v.y, w, acc.y);
        acc.z = fmaf(v.z, w, acc.z); acc.w = fmaf(v.w, w, acc.w);
    }
    g_hnew4[node * 16 + p] = acc;
}

// ---------------------------------------------------------------------------
// prep — bf16 hi/lo weight image + fused biases (unchanged).
// ---------------------------------------------------------------------------
__global__ void prep_kernel(const float* __restrict__ Wih,
                            const float* __restrict__ Whh,
                            const float* __restrict__ bih,
                            const float* __restrict__ bhh) {
    int idx = blockIdx.x * blockDim.x + threadIdx.x;   // 256 cols' x 32 quads
    if (idx < 8192) {
        int colp = idx >> 5, q = idx & 31;             // q: 4-k quad, q<16 -> x half
        int j = colp >> 2, g = colp & 3;
        int kk = (q & 15) * 4;                         // k within 64-half
        bool isX = (q < 16);
        float4 v = make_float4(0.f, 0.f, 0.f, 0.f);
        const float* srcRow = nullptr;
        if (g == 0)      srcRow = isX ? &Wih[j * 64]         : &Whh[j * 64];
        else if (g == 1) srcRow = isX ? &Wih[(64 + j) * 64]  : &Whh[(64 + j) * 64];
        else if (g == 2) srcRow = isX ? &Wih[(128 + j) * 64] : nullptr;
        else             srcRow = isX ? nullptr              : &Whh[(128 + j) * 64];
        if (srcRow) v = *(const float4*)(srcRow + kk);

        uint32_t h01 = cvtbf2(v.y, v.x), h23 = cvtbf2(v.w, v.z);
        uint32_t l01 = cvtbf2(v.y - bfhi_f(h01), v.x - bflo_f(h01));
        uint32_t l23 = cvtbf2(v.w - bfhi_f(h23), v.z - bflo_f(h23));
        uint32_t off = (uint32_t)colp * STRIDE_A + ((q >> 1) << 4) + ((q & 1) << 3);
        *(uint2*)(g_Bimg + off)          = make_uint2(h01, h23);
        *(uint2*)(g_Bimg + off + B_HALF) = make_uint2(l01, l23);
    }
    if (idx < 64) {
        g_biasf[idx * 4 + 0] = bih[idx] + bhh[idx];
        g_biasf[idx * 4 + 1] = bih[64 + idx] + bhh[64 + idx];
        g_biasf[idx * 4 + 2] = bih[128 + idx];
        g_biasf[idx * 4 + 3] = bhh[128 + idx];
    }
}

// ---------------------------------------------------------------------------
// GEMM + GRU epilogue: warp-independent 16-row tiles (R7, unchanged).
// ---------------------------------------------------------------------------
__global__ void __launch_bounds__(256, 1)
gemm_gru_kernel(const float4* __restrict__ h4, float* __restrict__ out,
                int Nn, int n_tiles16) {
    extern __shared__ __align__(16) char smem[];
    const uint32_t sb = smem_u32(smem);
    const int tid = threadIdx.x;
    const int w = tid >> 5, l = tid & 31;
    const int gid = l >> 2, tg = l & 3;

    // --- B image + bias -> SMEM (linear, pre-formatted) ---
    {
        const uint4* srcB = (const uint4*)g_Bimg;
        uint4* dstB = (uint4*)(smem + SM_B);
        for (int i = tid; i < (2 * B_HALF) / 16; i += 256) dstB[i] = srcB[i];
        ((float*)smem)[tid] = g_biasf[tid];
    }
    __syncthreads();

    const int warpA_off = SM_A + w * A_WARP;           // warp-private A region
    const int sel = l >> 3;
    const uint32_t a_base = sb + (uint32_t)warpA_off +
        (uint32_t)((((sel & 1) << 3) + (l & 7)) * STRIDE_A + ((sel >> 1) << 4));
    const uint32_t b_base = sb + SM_B +
        (uint32_t)((((sel >> 1) << 3) + (l & 7)) * STRIDE_A + ((sel & 1) << 4));

    const bool ev = !(l & 1);
    const int nodeloc = gid + (ev ? 0 : 8);

    for (int tw = blockIdx.x * 8 + w; tw < n_tiles16; tw += gridDim.x * 8) {
        const int m0 = tw << 4;

        // --- A tile (16 rows, warp-private): f32 -> bf16 hi/lo split ---
#pragma unroll
        for (int it = 0; it < 16; it++) {
            int node = m0 + it;
            int kq = l;                               // 4-k quad; <16: hnew, >=16: h
            float4 v = make_float4(0.f, 0.f, 0.f, 0.f);
            if (node < Nn)
                v = (kq < 16) ? g_hnew4[node * 16 + kq]
                              : __ldg(&h4[node * 16 + (kq - 16)]);
            uint32_t h01 = cvtbf2(v.y, v.x), h23 = cvtbf2(v.w, v.z);
            uint32_t l01 = cvtbf2(v.y - bfhi_f(h01), v.x - bflo_f(h01));
            uint32_t l23 = cvtbf2(v.w - bfhi_f(h23), v.z - bflo_f(h23));
            uint32_t off = (uint32_t)warpA_off + (uint32_t)it * STRIDE_A +
                           ((uint32_t)(kq >> 1) << 4) + ((uint32_t)(kq & 1) << 3);
            *(uint2*)(smem + off)            = make_uint2(h01, h23);
            *(uint2*)(smem + off + A_HALF_W) = make_uint2(l01, l23);
        }
        __syncwarp();

        // --- GEMM: 3 split passes, 8 k-steps, 32 n-blocks ---
        float acc[128];
#pragma unroll
        for (int i = 0; i < 128; i++) acc[i] = 0.f;

#pragma unroll 1
        for (int p = 0; p < 3; p++) {
            const uint32_t ab = a_base + ((p == 2) ? (uint32_t)A_HALF_W : 0u);
            const uint32_t bb = b_base + ((p == 1) ? (uint32_t)B_HALF : 0u);
#pragma unroll
            for (int s = 0; s < 8; s++) {
                uint32_t a0, a1, a2, a3;
                LDSM4(a0, a1, a2, a3, ab + (uint32_t)s * 32);
#pragma unroll
                for (int nb = 0; nb < 16; nb++) {
                    uint32_t b0, b1, b2, b3;
                    LDSM4(b0, b1, b2, b3,
                          bb + (uint32_t)nb * (16 * STRIDE_A) + (uint32_t)s * 32);
                    MMA16816(&acc[(nb * 2) * 4],     a0, a1, a2, a3, b0, b1);
                    MMA16816(&acc[(nb * 2 + 1) * 4], a0, a1, a2, a3, b2, b3);
                }
            }
        }

        // --- Epilogue phase 1: gate math; output stashed into acc[fn*4] ---
#pragma unroll
        for (int fn = 0; fn < 32; fn++) {
            int jj = fn * 2 + (tg >> 1);
            float4 b4 = *(const float4*)(smem + SM_BIAS + jj * 16);
            float s0 = acc[fn * 4], s1 = acc[fn * 4 + 1];
            float s2 = acc[fn * 4 + 2], s3 = acc[fn * 4 + 3];
            float t0 = __shfl_xor_sync(0xffffffffu, s0, 1);
            float t1 = __shfl_xor_sync(0xffffffffu, s1, 1);
            float t2 = __shfl_xor_sync(0xffffffffu, s2, 1);
            float t3 = __shfl_xor_sync(0xffffffffu, s3, 1);
            float rs = ev ? s0 : t2;
            float zs = ev ? s1 : t3;
            float is = ev ? t0 : s2;
            float hs = ev ? t1 : s3;
            float r  = sigmoidf_fast(rs + b4.x);
            float z  = sigmoidf_fast(zs + b4.y);
            float nn = tanhf_fast(is + b4.z + r * (hs + b4.w));
            int kcol = 64 + jj;                 // h lives in A cols 64..127
            uint32_t hoff = (uint32_t)warpA_off + (uint32_t)nodeloc * STRIDE_A +
                            ((uint32_t)(kcol >> 3) << 4) + ((uint32_t)(kcol & 7) << 1);
            uint32_t hib = *(const unsigned short*)(smem + hoff);
            uint32_t lob = *(const unsigned short*)(smem + hoff + A_HALF_W);
            float hv = __uint_as_float(hib << 16) + __uint_as_float(lob << 16);
            acc[fn * 4] = (1.f - z) * nn + z * hv;
        }
        __syncwarp();

        // --- Epilogue phase 2: stage into warp-private SMEM (XOR swizzle) ---
        const uint32_t pat = ((uint32_t)nodeloc & 7) << 5;
#pragma unroll
        for (int fn = 0; fn < 32; fn++) {
            int jj = fn * 2 + (tg >> 1);
            uint32_t sa = (uint32_t)warpA_off + (uint32_t)nodeloc * 256 +
                          (((uint32_t)jj << 2) ^ pat);
            *(float*)(smem + sa) = acc[fn * 4];
        }
        __syncwarp();

        // --- Epilogue phase 3: coalesced 16B stores ---
#pragma unroll
        for (int it = 0; it < 8; it++) {
            int idx = it * 32 + l;
            int nl = idx >> 4, c16 = idx & 15;
            uint32_t ra = (uint32_t)warpA_off + (uint32_t)nl * 256 +
                          (((uint32_t)c16 << 4) ^ (((uint32_t)nl & 7) << 5));
            uint4 v = *(const uint4*)(smem + ra);
            int node = m0 + nl;
            if (node < Nn) *(uint4*)(out + (size_t)node * 64 + c16 * 4) = v;
        }
        __syncwarp();   // staging/A safe to rewrite next tile
    }
}

// ---------------------------------------------------------------------------
// Launch
// ---------------------------------------------------------------------------
extern "C" void kernel_launch(void* const* d_in, const int* in_sizes, int n_in,
                              void* d_out, int out_size) {
    const float* h   = (const float*)d_in[0];
    const float* ew  = (const float*)d_in[1];
    const float* Wih = (const float*)d_in[2];
    const float* Whh = (const float*)d_in[3];
    const float* bih = (const float*)d_in[4];
    const float* bhh = (const float*)d_in[5];
    const void* srcp = d_in[6];
    const void* dstp = d_in[7];
    float* out       = (float*)d_out;

    int E  = in_sizes[1];
    int Nn = in_sizes[0] / D;
    int n_tiles16 = (Nn + 15) / 16;
    int eblocks = (E + 255) / 256;

    detect_kernel<<<1, 32>>>((const unsigned long long*)srcp,
                             (const unsigned long long*)dstp);

    // CSR build
    zcnt_kernel<<<(Nn + 255) / 256, 256>>>(Nn);
    hist_kernel<<<eblocks, 256>>>(dstp, E);
    scan_kernel<<<1, 1024>>>(Nn, E);
    reorder_kernel<<<eblocks, 256>>>(srcp, dstp, ew, E);

    prep_kernel<<<32, 256>>>(Wih, Whh, bih, bhh);

    // Atomic-free accumulate (writes every row; replaces zero + RED scatter)
    accum_kernel<<<(Nn * 16 + 255) / 256, 256>>>((const float4*)h, Nn);

    cudaFuncSetAttribute(gemm_gru_kernel,
                         cudaFuncAttributeMaxDynamicSharedMemorySize, SM_TOT);
    gemm_gru_kernel<<<148, 256, SM_TOT>>>((const float4*)h, out, Nn, n_tiles16);
}

// round 9
// speedup vs baseline: 2.8099x; 2.8099x over previous
#include <cuda_runtime.h>
#include <cstdint>

#define D 64
#define NMAX 100000
#define EMAX 1664000

// ---------------------------------------------------------------------------
// Device scratch
// ---------------------------------------------------------------------------
__device__ float4  g_hnew4[NMAX * (D / 4)];   // h_new result (25.6 MB)
__device__ uint2   g_rec[EMAX];               // CSR records: (src, w bits)
__device__ int     g_cnt[NMAX];               // histogram / write cursors
__device__ int     g_off[NMAX + 1];           // CSR row offsets
__device__ int     g_blk[128];                // block totals for scan
__device__ int     g_blkoff[128];             // block exclusive offsets
__device__ uint8_t g_Bimg[139264];            // bf16 hi+lo weight image
__device__ float   g_biasf[256];              // fused biases, col' = j*4+gate
__device__ int     g_is32;                    // src/dst dtype flag

// SMEM map for the GEMM kernel
#define STRIDE_A 272            // 128 k * 2B padded to 17*16B (ldmatrix conflict-free)
#define A_HALF_W 4352           // per-warp A half: 16 rows * 272
#define A_WARP   8704           // per-warp A region (hi + lo)
#define B_HALF   69632          // 256 rows * 272
#define SM_BIAS  0
#define SM_A     1024
#define SM_B     (SM_A + 8 * A_WARP)          // 70656
#define SM_TOT   (SM_B + 2 * B_HALF)          // 209920

// ---------------------------------------------------------------------------
// Helpers
// ---------------------------------------------------------------------------
__device__ __forceinline__ uint32_t smem_u32(const void* p) {
    uint32_t a;
    asm("{ .reg .u64 t; cvta.to.shared.u64 t, %1; cvt.u32.u64 %0, t; }"
        : "=r"(a) : "l"(p));
    return a;
}
__device__ __forceinline__ uint32_t cvtbf2(float hi, float lo) {
    uint32_t d;
    asm("cvt.rn.bf16x2.f32 %0, %1, %2;" : "=r"(d) : "f"(hi), "f"(lo));
    return d;
}
__device__ __forceinline__ float bflo_f(uint32_t p) { return __uint_as_float(p << 16); }
__device__ __forceinline__ float bfhi_f(uint32_t p) { return __uint_as_float(p & 0xffff0000u); }

__device__ __forceinline__ float sigmoidf_fast(float x) {
    return __fdividef(1.0f, 1.0f + __expf(-x));
}
__device__ __forceinline__ float tanhf_fast(float x) {
    return 1.0f - __fdividef(2.0f, __expf(2.0f * x) + 1.0f);
}

#define LDSM4(r0, r1, r2, r3, a)                                            \
    asm volatile("ldmatrix.sync.aligned.m8n8.x4.shared.b16 {%0,%1,%2,%3}, [%4];" \
                 : "=r"(r0), "=r"(r1), "=r"(r2), "=r"(r3) : "r"(a))

#define MMA16816(c, a0, a1, a2, a3, b0, b1)                                 \
    asm volatile("mma.sync.aligned.m16n8k16.row.col.f32.bf16.bf16.f32 "     \
                 "{%0,%1,%2,%3}, {%4,%5,%6,%7}, {%8,%9}, {%0,%1,%2,%3};"    \
                 : "+f"((c)[0]), "+f"((c)[1]), "+f"((c)[2]), "+f"((c)[3])   \
                 : "r"(a0), "r"(a1), "r"(a2), "r"(a3), "r"(b0), "r"(b1))

// ---------------------------------------------------------------------------
// Kernel 0: index dtype detection (int32 vs int64 node ids)
// ---------------------------------------------------------------------------
__global__ void detect_kernel(const unsigned long long* __restrict__ src,
                              const unsigned long long* __restrict__ dst) {
    if (threadIdx.x == 0 && blockIdx.x == 0) {
        unsigned long long acc = 0;
#pragma unroll
        for (int i = 0; i < 8; i++) acc |= (src[i] >> 32) | (dst[i] >> 32);
        g_is32 = (acc != 0ULL) ? 1 : 0;
    }
}

// ---------------------------------------------------------------------------
// CSR build
// ---------------------------------------------------------------------------
__global__ void zcnt_kernel(int Nn) {
    int i = blockIdx.x * blockDim.x + threadIdx.x;
    if (i < Nn) g_cnt[i] = 0;
}

__global__ void hist_kernel(const void* __restrict__ dstp, int E) {
    int e = blockIdx.x * blockDim.x + threadIdx.x;
    if (e >= E) return;
    int d = g_is32 ? ((const int*)dstp)[e]
                   : (int)((const long long*)dstp)[e];
    atomicAdd(&g_cnt[d], 1);
}

// Hierarchical scan A: 1024-wide block scan; g_off[i] = within-block exclusive,
// g_blk[b] = block total.
__global__ void __launch_bounds__(1024) scanA_kernel(int Nn) {
    __shared__ int ws[32];
    const int t = threadIdx.x, lane = t & 31, wid = t >> 5;
    const int i = blockIdx.x * 1024 + t;
    int c = (i < Nn) ? g_cnt[i] : 0;

    int v = c;
#pragma unroll
    for (int d = 1; d < 32; d <<= 1) {
        int n = __shfl_up_sync(0xffffffffu, v, d);
        if (lane >= d) v += n;
    }
    if (lane == 31) ws[wid] = v;
    __syncthreads();
    if (wid == 0) {
        int wv = ws[lane];
#pragma unroll
        for (int d = 1; d < 32; d <<= 1) {
            int n = __shfl_up_sync(0xffffffffu, wv, d);
            if (lane >= d) wv += n;
        }
        ws[lane] = wv;
    }
    __syncthreads();
    int incl = v + (wid ? ws[wid - 1] : 0);
    if (i < Nn) g_off[i] = incl - c;
    if (t == 1023) g_blk[blockIdx.x] = incl;
}

// Hierarchical scan B: one 128-thread block scans the <=128 block totals.
__global__ void __launch_bounds__(128) scanB_kernel(int nb) {
    __shared__ int ws[4];
    const int t = threadIdx.x, lane = t & 31, wid = t >> 5;
    int c = (t < nb) ? g_blk[t] : 0;
    int v = c;
#pragma unroll
    for (int d = 1; d < 32; d <<= 1) {
        int n = __shfl_up_sync(0xffffffffu, v, d);
        if (lane >= d) v += n;
    }
    if (lane == 31) ws[wid] = v;
    __syncthreads();
    int add = 0;
#pragma unroll
    for (int k = 0; k < 4; k++) add += (k < wid) ? ws[k] : 0;
    g_blkoff[t] = v + add - c;   // exclusive
}

// Hierarchical scan C: add block offsets; set cursors; cap row.
__global__ void scanC_kernel(int Nn, int E) {
    int i = blockIdx.x * blockDim.x + threadIdx.x;
    if (i < Nn) {
        int off = g_off[i] + g_blkoff[i >> 10];
        g_off[i] = off;
        g_cnt[i] = off;
    }
    if (i == 0) g_off[Nn] = E;
}

__global__ void reorder_kernel(const void* __restrict__ srcp,
                               const void* __restrict__ dstp,
                               const float* __restrict__ ew, int E) {
    int e = blockIdx.x * blockDim.x + threadIdx.x;
    if (e >= E) return;
    int s, d;
    if (g_is32) {
        s = ((const int*)srcp)[e];
        d = ((const int*)dstp)[e];
    } else {
        s = (int)((const long long*)srcp)[e];
        d = (int)((const long long*)dstp)[e];
    }
    int pos = atomicAdd(&g_cnt[d], 1);
    g_rec[pos] = make_uint2((uint32_t)s, __float_as_uint(__ldg(&ew[e])));
}

// ---------------------------------------------------------------------------
// Accumulate: half-warp per node, lane owns a float4 part; unroll-4 for MLP.
// ---------------------------------------------------------------------------
__global__ void __launch_bounds__(256) accum_kernel(const float4* __restrict__ h4,
                                                    int Nn) {
    int gid = blockIdx.x * blockDim.x + threadIdx.x;
    int node = gid >> 4, p = gid & 15;
    if (node >= Nn) return;
    int e = g_off[node];
    const int end = g_off[node + 1];
    float4 acc = make_float4(0.f, 0.f, 0.f, 0.f);

    for (; e + 4 <= end; e += 4) {
        uint2 r0 = g_rec[e],     r1 = g_rec[e + 1];
        uint2 r2 = g_rec[e + 2], r3 = g_rec[e + 3];
        float4 v0 = __ldg(&h4[(size_t)r0.x * 16 + p]);
        float4 v1 = __ldg(&h4[(size_t)r1.x * 16 + p]);
        float4 v2 = __ldg(&h4[(size_t)r2.x * 16 + p]);
        float4 v3 = __ldg(&h4[(size_t)r3.x * 16 + p]);
        float w0 = __uint_as_float(r0.y), w1 = __uint_as_float(r1.y);
        float w2 = __uint_as_float(r2.y), w3 = __uint_as_float(r3.y);
        acc.x = fmaf(v0.x, w0, acc.x); acc.y = fmaf(v0.y, w0, acc.y);
        acc.z = fmaf(v0.z, w0, acc.z); acc.w = fmaf(v0.w, w0, acc.w);
        acc.x = fmaf(v1.x, w1, acc.x); acc.y = fmaf(v1.y, w1, acc.y);
        acc.z = fmaf(v1.z, w1, acc.z); acc.w = fmaf(v1.w, w1, acc.w);
        acc.x = fmaf(v2.x, w2, acc.x); acc.y = fmaf(v2.y, w2, acc.y);
        acc.z = fmaf(v2.z, w2, acc.z); acc.w = fmaf(v2.w, w2, acc.w);
        acc.x = fmaf(v3.x, w3, acc.x); acc.y = fmaf(v3.y, w3, acc.y);
        acc.z = fmaf(v3.z, w3, acc.z); acc.w = fmaf(v3.w, w3, acc.w);
    }
    for (; e < end; e++) {
        uint2 r = g_rec[e];
        float4 v = __ldg(&h4[(size_t)r.x * 16 + p]);
        float w = __uint_as_float(r.y);
        acc.x = fmaf(v.x, w, acc.x); acc.y = fmaf(v.y, w, acc.y);
        acc.z = fmaf(v.z, w, acc.z); acc.w = fmaf(v.w, w, acc.w);
    }
    g_hnew4[node * 16 + p] = acc;
}

// ---------------------------------------------------------------------------
// prep — bf16 hi/lo weight image + fused biases (unchanged).
// ---------------------------------------------------------------------------
__global__ void prep_kernel(const float* __restrict__ Wih,
                            const float* __restrict__ Whh,
                            const float* __restrict__ bih,
                            const float* __restrict__ bhh) {
    int idx = blockIdx.x * blockDim.x + threadIdx.x;   // 256 cols' x 32 quads
    if (idx < 8192) {
        int colp = idx >> 5, q = idx & 31;             // q: 4-k quad, q<16 -> x half
        int j = colp >> 2, g = colp & 3;
        int kk = (q & 15) * 4;                         // k within 64-half
        bool isX = (q < 16);
        float4 v = make_float4(0.f, 0.f, 0.f, 0.f);
        const float* srcRow = nullptr;
        if (g == 0)      srcRow = isX ? &Wih[j * 64]         : &Whh[j * 64];
        else if (g == 1) srcRow = isX ? &Wih[(64 + j) * 64]  : &Whh[(64 + j) * 64];
        else if (g == 2) srcRow = isX ? &Wih[(128 + j) * 64] : nullptr;
        else             srcRow = isX ? nullptr              : &Whh[(128 + j) * 64];
        if (srcRow) v = *(const float4*)(srcRow + kk);

        uint32_t h01 = cvtbf2(v.y, v.x), h23 = cvtbf2(v.w, v.z);
        uint32_t l01 = cvtbf2(v.y - bfhi_f(h01), v.x - bflo_f(h01));
        uint32_t l23 = cvtbf2(v.w - bfhi_f(h23), v.z - bflo_f(h23));
        uint32_t off = (uint32_t)colp * STRIDE_A + ((q >> 1) << 4) + ((q & 1) << 3);
        *(uint2*)(g_Bimg + off)          = make_uint2(h01, h23);
        *(uint2*)(g_Bimg + off + B_HALF) = make_uint2(l01, l23);
    }
    if (idx < 64) {
        g_biasf[idx * 4 + 0] = bih[idx] + bhh[idx];
        g_biasf[idx * 4 + 1] = bih[64 + idx] + bhh[64 + idx];
        g_biasf[idx * 4 + 2] = bih[128 + idx];
        g_biasf[idx * 4 + 3] = bhh[128 + idx];
    }
}

// ---------------------------------------------------------------------------
// GEMM + GRU epilogue: warp-independent 16-row tiles; 2-group split passes
// (group 0: Bhi loaded once serving Ahi*Bhi + Alo*Bhi; group 1: Ahi*Blo) —
// B LDSM traffic x 2/3 vs the 3-pass form.
// ---------------------------------------------------------------------------
__global__ void __launch_bounds__(256, 1)
gemm_gru_kernel(const float4* __restrict__ h4, float* __restrict__ out,
                int Nn, int n_tiles16) {
    extern __shared__ __align__(16) char smem[];
    const uint32_t sb = smem_u32(smem);
    const int tid = threadIdx.x;
    const int w = tid >> 5, l = tid & 31;
    const int gid = l >> 2, tg = l & 3;

    // --- B image + bias -> SMEM (linear, pre-formatted) ---
    {
        const uint4* srcB = (const uint4*)g_Bimg;
        uint4* dstB = (uint4*)(smem + SM_B);
        for (int i = tid; i < (2 * B_HALF) / 16; i += 256) dstB[i] = srcB[i];
        ((float*)smem)[tid] = g_biasf[tid];
    }
    __syncthreads();

    const int warpA_off = SM_A + w * A_WARP;           // warp-private A region
    const int sel = l >> 3;
    const uint32_t a_base = sb + (uint32_t)warpA_off +
        (uint32_t)((((sel & 1) << 3) + (l & 7)) * STRIDE_A + ((sel >> 1) << 4));
    const uint32_t b_base = sb + SM_B +
        (uint32_t)((((sel >> 1) << 3) + (l & 7)) * STRIDE_A + ((sel & 1) << 4));

    const bool ev = !(l & 1);
    const int nodeloc = gid + (ev ? 0 : 8);

    for (int tw = blockIdx.x * 8 + w; tw < n_tiles16; tw += gridDim.x * 8) {
        const int m0 = tw << 4;

        // --- A tile (16 rows, warp-private): f32 -> bf16 hi/lo split ---
#pragma unroll
        for (int it = 0; it < 16; it++) {
            int node = m0 + it;
            int kq = l;                               // 4-k quad; <16: hnew, >=16: h
            float4 v = make_float4(0.f, 0.f, 0.f, 0.f);
            if (node < Nn)
                v = (kq < 16) ? g_hnew4[node * 16 + kq]
                              : __ldg(&h4[node * 16 + (kq - 16)]);
            uint32_t h01 = cvtbf2(v.y, v.x), h23 = cvtbf2(v.w, v.z);
            uint32_t l01 = cvtbf2(v.y - bfhi_f(h01), v.x - bflo_f(h01));
            uint32_t l23 = cvtbf2(v.w - bfhi_f(h23), v.z - bflo_f(h23));
            uint32_t off = (uint32_t)warpA_off + (uint32_t)it * STRIDE_A +
                           ((uint32_t)(kq >> 1) << 4) + ((uint32_t)(kq & 1) << 3);
            *(uint2*)(smem + off)            = make_uint2(h01, h23);
            *(uint2*)(smem + off + A_HALF_W) = make_uint2(l01, l23);
        }
        __syncwarp();

        float acc[128];
#pragma unroll
        for (int i = 0; i < 128; i++) acc[i] = 0.f;

        // --- Group 0: (Ahi + Alo) x Bhi — one Bhi load serves 4 MMAs ---
#pragma unroll 1
        for (int s = 0; s < 8; s++) {
            uint32_t ah0, ah1, ah2, ah3, al0, al1, al2, al3;
            LDSM4(ah0, ah1, ah2, ah3, a_base + (uint32_t)s * 32);
            LDSM4(al0, al1, al2, al3, a_base + A_HALF_W + (uint32_t)s * 32);
#pragma unroll
            for (int nb = 0; nb < 16; nb++) {
                uint32_t b0, b1, b2, b3;
                LDSM4(b0, b1, b2, b3,
                      b_base + (uint32_t)nb * (16 * STRIDE_A) + (uint32_t)s * 32);
                float* c0 = &acc[(nb * 2) * 4];
                float* c1 = &acc[(nb * 2 + 1) * 4];
                MMA16816(c0, ah0, ah1, ah2, ah3, b0, b1);
                MMA16816(c1, ah0, ah1, ah2, ah3, b2, b3);
                MMA16816(c0, al0, al1, al2, al3, b0, b1);
                MMA16816(c1, al0, al1, al2, al3, b2, b3);
            }
        }
        // --- Group 1: Ahi x Blo ---
#pragma unroll 1
        for (int s = 0; s < 8; s++) {
            uint32_t a0, a1, a2, a3;
            LDSM4(a0, a1, a2, a3, a_base + (uint32_t)s * 32);
#pragma unroll
            for (int nb = 0; nb < 16; nb++) {
                uint32_t b0, b1, b2, b3;
                LDSM4(b0, b1, b2, b3, b_base + B_HALF +
                      (uint32_t)nb * (16 * STRIDE_A) + (uint32_t)s * 32);
                MMA16816(&acc[(nb * 2) * 4],     a0, a1, a2, a3, b0, b1);
                MMA16816(&acc[(nb * 2 + 1) * 4], a0, a1, a2, a3, b2, b3);
            }
        }

        // --- Epilogue phase 1: gate math; output stashed into acc[fn*4] ---
#pragma unroll
        for (int fn = 0; fn < 32; fn++) {
            int jj = fn * 2 + (tg >> 1);
            float4 b4 = *(const float4*)(smem + SM_BIAS + jj * 16);
            float s0 = acc[fn * 4], s1 = acc[fn * 4 + 1];
            float s2 = acc[fn * 4 + 2], s3 = acc[fn * 4 + 3];
            float t0 = __shfl_xor_sync(0xffffffffu, s0, 1);
            float t1 = __shfl_xor_sync(0xffffffffu, s1, 1);
            float t2 = __shfl_xor_sync(0xffffffffu, s2, 1);
            float t3 = __shfl_xor_sync(0xffffffffu, s3, 1);
            float rs = ev ? s0 : t2;
            float zs = ev ? s1 : t3;
            float is = ev ? t0 : s2;
            float hs = ev ? t1 : s3;
            float r  = sigmoidf_fast(rs + b4.x);
            float z  = sigmoidf_fast(zs + b4.y);
            float nn = tanhf_fast(is + b4.z + r * (hs + b4.w));
            int kcol = 64 + jj;                 // h lives in A cols 64..127
            uint32_t hoff = (uint32_t)warpA_off + (uint32_t)nodeloc * STRIDE_A +
                            ((uint32_t)(kcol >> 3) << 4) + ((uint32_t)(kcol & 7) << 1);
            uint32_t hib = *(const unsigned short*)(smem + hoff);
            uint32_t lob = *(const unsigned short*)(smem + hoff + A_HALF_W);
            float hv = __uint_as_float(hib << 16) + __uint_as_float(lob << 16);
            acc[fn * 4] = (1.f - z) * nn + z * hv;
        }
        __syncwarp();

        // --- Epilogue phase 2: stage into warp-private SMEM (XOR swizzle) ---
        const uint32_t pat = ((uint32_t)nodeloc & 7) << 5;
#pragma unroll
        for (int fn = 0; fn < 32; fn++) {
            int jj = fn * 2 + (tg >> 1);
            uint32_t sa = (uint32_t)warpA_off + (uint32_t)nodeloc * 256 +
                          (((uint32_t)jj << 2) ^ pat);
            *(float*)(smem + sa) = acc[fn * 4];
        }
        __syncwarp();

        // --- Epilogue phase 3: coalesced 16B stores ---
#pragma unroll
        for (int it = 0; it < 8; it++) {
            int idx = it * 32 + l;
            int nl = idx >> 4, c16 = idx & 15;
            uint32_t ra = (uint32_t)warpA_off + (uint32_t)nl * 256 +
                          (((uint32_t)c16 << 4) ^ (((uint32_t)nl & 7) << 5));
            uint4 v = *(const uint4*)(smem + ra);
            int node = m0 + nl;
            if (node < Nn) *(uint4*)(out + (size_t)node * 64 + c16 * 4) = v;
        }
        __syncwarp();   // staging/A safe to rewrite next tile
    }
}

// ---------------------------------------------------------------------------
// Launch
// ---------------------------------------------------------------------------
extern "C" void kernel_launch(void* const* d_in, const int* in_sizes, int n_in,
                              void* d_out, int out_size) {
    const float* h   = (const float*)d_in[0];
    const float* ew  = (const float*)d_in[1];
    const float* Wih = (const float*)d_in[2];
    const float* Whh = (const float*)d_in[3];
    const float* bih = (const float*)d_in[4];
    const float* bhh = (const float*)d_in[5];
    const void* srcp = d_in[6];
    const void* dstp = d_in[7];
    float* out       = (float*)d_out;

    int E  = in_sizes[1];
    int Nn = in_sizes[0] / D;
    int n_tiles16 = (Nn + 15) / 16;
    int eblocks = (E + 255) / 256;
    int nb = (Nn + 1023) / 1024;

    detect_kernel<<<1, 32>>>((const unsigned long long*)srcp,
                             (const unsigned long long*)dstp);

    // CSR build (hierarchical scan)
    zcnt_kernel<<<(Nn + 255) / 256, 256>>>(Nn);
    hist_kernel<<<eblocks, 256>>>(dstp, E);
    scanA_kernel<<<nb, 1024>>>(Nn);
    scanB_kernel<<<1, 128>>>(nb);
    scanC_kernel<<<(Nn + 255) / 256, 256>>>(Nn, E);
    reorder_kernel<<<eblocks, 256>>>(srcp, dstp, ew, E);

    prep_kernel<<<32, 256>>>(Wih, Whh, bih, bhh);

    accum_kernel<<<(Nn * 16 + 255) / 256, 256>>>((const float4*)h, Nn);

    cudaFuncSetAttribute(gemm_gru_kernel,
                         cudaFuncAttributeMaxDynamicSharedMemorySize, SM_TOT);
    gemm_gru_kernel<<<148, 256, SM_TOT>>>((const float4*)h, out, Nn, n_tiles16);
}

// round 10
// speedup vs baseline: 3.0774x; 1.0952x over previous
#include <cuda_runtime.h>
#include <cstdint>

#define D 64
#define NMAX 100000
#define EMAX 1664000

// ---------------------------------------------------------------------------
// Device scratch
// ---------------------------------------------------------------------------
__device__ float4  g_hnew4[NMAX * (D / 4)];   // h_new result (25.6 MB)
__device__ uint2   g_rec[EMAX];               // CSR records: (src, w bits)
__device__ int     g_cnt[NMAX];               // histogram / write cursors
__device__ int     g_off[NMAX + 1];           // CSR row offsets
__device__ int     g_blk[128];                // block totals for scan
__device__ int     g_blkoff[128];             // block exclusive offsets
__device__ uint8_t g_Bimg[139264];            // bf16 hi+lo weight image (grouped cols)
__device__ float   g_biasf[256];              // biases: [r(64)|z(64)|i_n(64)|h_n(64)]
__device__ int     g_is32;                    // src/dst dtype flag

// SMEM map for the GEMM kernel
#define STRIDE_A 272            // 128 k * 2B padded to 17*16B (ldmatrix conflict-free)
#define A_HALF_W 4352           // per-warp A half: 16 rows * 272
#define A_WARP   8704           // per-warp A region (hi + lo)
#define B_HALF   69632          // 256 rows * 272
#define SM_BIAS  0
#define SM_A     1024
#define SM_B     (SM_A + 8 * A_WARP)          // 70656
#define SM_TOT   (SM_B + 2 * B_HALF)          // 209920

// ---------------------------------------------------------------------------
// Helpers
// ---------------------------------------------------------------------------
__device__ __forceinline__ uint32_t smem_u32(const void* p) {
    uint32_t a;
    asm("{ .reg .u64 t; cvta.to.shared.u64 t, %1; cvt.u32.u64 %0, t; }"
        : "=r"(a) : "l"(p));
    return a;
}
__device__ __forceinline__ uint32_t cvtbf2(float hi, float lo) {
    uint32_t d;
    asm("cvt.rn.bf16x2.f32 %0, %1, %2;" : "=r"(d) : "f"(hi), "f"(lo));
    return d;
}
__device__ __forceinline__ float bflo_f(uint32_t p) { return __uint_as_float(p << 16); }
__device__ __forceinline__ float bfhi_f(uint32_t p) { return __uint_as_float(p & 0xffff0000u); }

__device__ __forceinline__ float sigmoidf_fast(float x) {
    return __fdividef(1.0f, 1.0f + __expf(-x));
}
__device__ __forceinline__ float tanhf_fast(float x) {
    return 1.0f - __fdividef(2.0f, __expf(2.0f * x) + 1.0f);
}

#define LDSM4(r0, r1, r2, r3, a)                                            \
    asm volatile("ldmatrix.sync.aligned.m8n8.x4.shared.b16 {%0,%1,%2,%3}, [%4];" \
                 : "=r"(r0), "=r"(r1), "=r"(r2), "=r"(r3) : "r"(a))

#define MMA16816(c, a0, a1, a2, a3, b0, b1)                                 \
    asm volatile("mma.sync.aligned.m16n8k16.row.col.f32.bf16.bf16.f32 "     \
                 "{%0,%1,%2,%3}, {%4,%5,%6,%7}, {%8,%9}, {%0,%1,%2,%3};"    \
                 : "+f"((c)[0]), "+f"((c)[1]), "+f"((c)[2]), "+f"((c)[3])   \
                 : "r"(a0), "r"(a1), "r"(a2), "r"(a3), "r"(b0), "r"(b1))

// ---------------------------------------------------------------------------
// zcnt (+ fused index-dtype detection in block 0)
// ---------------------------------------------------------------------------
__global__ void zcnt_kernel(const unsigned long long* __restrict__ src,
                            const unsigned long long* __restrict__ dst, int Nn) {
    int i = blockIdx.x * blockDim.x + threadIdx.x;
    if (i < Nn) g_cnt[i] = 0;
    if (i == 0) {
        unsigned long long acc = 0;
#pragma unroll
        for (int k = 0; k < 8; k++) acc |= (src[k] >> 32) | (dst[k] >> 32);
        g_is32 = (acc != 0ULL) ? 1 : 0;
    }
}

__global__ void hist_kernel(const void* __restrict__ dstp, int E) {
    int e = blockIdx.x * blockDim.x + threadIdx.x;
    if (e >= E) return;
    int d = g_is32 ? ((const int*)dstp)[e]
                   : (int)((const long long*)dstp)[e];
    atomicAdd(&g_cnt[d], 1);
}

// Hierarchical scan A: 1024-wide block scan.
__global__ void __launch_bounds__(1024) scanA_kernel(int Nn) {
    __shared__ int ws[32];
    const int t = threadIdx.x, lane = t & 31, wid = t >> 5;
    const int i = blockIdx.x * 1024 + t;
    int c = (i < Nn) ? g_cnt[i] : 0;
    int v = c;
#pragma unroll
    for (int d = 1; d < 32; d <<= 1) {
        int n = __shfl_up_sync(0xffffffffu, v, d);
        if (lane >= d) v += n;
    }
    if (lane == 31) ws[wid] = v;
    __syncthreads();
    if (wid == 0) {
        int wv = ws[lane];
#pragma unroll
        for (int d = 1; d < 32; d <<= 1) {
            int n = __shfl_up_sync(0xffffffffu, wv, d);
            if (lane >= d) wv += n;
        }
        ws[lane] = wv;
    }
    __syncthreads();
    int incl = v + (wid ? ws[wid - 1] : 0);
    if (i < Nn) g_off[i] = incl - c;
    if (t == 1023) g_blk[blockIdx.x] = incl;
}

__global__ void __launch_bounds__(128) scanB_kernel(int nb) {
    __shared__ int ws[4];
    const int t = threadIdx.x, lane = t & 31, wid = t >> 5;
    int c = (t < nb) ? g_blk[t] : 0;
    int v = c;
#pragma unroll
    for (int d = 1; d < 32; d <<= 1) {
        int n = __shfl_up_sync(0xffffffffu, v, d);
        if (lane >= d) v += n;
    }
    if (lane == 31) ws[wid] = v;
    __syncthreads();
    int add = 0;
#pragma unroll
    for (int k = 0; k < 4; k++) add += (k < wid) ? ws[k] : 0;
    g_blkoff[t] = v + add - c;
}

__global__ void scanC_kernel(int Nn, int E) {
    int i = blockIdx.x * blockDim.x + threadIdx.x;
    if (i < Nn) {
        int off = g_off[i] + g_blkoff[i >> 10];
        g_off[i] = off;
        g_cnt[i] = off;
    }
    if (i == 0) g_off[Nn] = E;
}

__global__ void reorder_kernel(const void* __restrict__ srcp,
                               const void* __restrict__ dstp,
                               const float* __restrict__ ew, int E) {
    int e = blockIdx.x * blockDim.x + threadIdx.x;
    if (e >= E) return;
    int s, d;
    if (g_is32) {
        s = ((const int*)srcp)[e];
        d = ((const int*)dstp)[e];
    } else {
        s = (int)((const long long*)srcp)[e];
        d = (int)((const long long*)dstp)[e];
    }
    int pos = atomicAdd(&g_cnt[d], 1);
    g_rec[pos] = make_uint2((uint32_t)s, __float_as_uint(__ldg(&ew[e])));
}

// ---------------------------------------------------------------------------
// Accumulate: half-warp per node, lane owns a float4 part; unroll-4 for MLP.
// ---------------------------------------------------------------------------
__global__ void __launch_bounds__(256) accum_kernel(const float4* __restrict__ h4,
                                                    int Nn) {
    int gid = blockIdx.x * blockDim.x + threadIdx.x;
    int node = gid >> 4, p = gid & 15;
    if (node >= Nn) return;
    int e = g_off[node];
    const int end = g_off[node + 1];
    float4 acc = make_float4(0.f, 0.f, 0.f, 0.f);

    for (; e + 4 <= end; e += 4) {
        uint2 r0 = g_rec[e],     r1 = g_rec[e + 1];
        uint2 r2 = g_rec[e + 2], r3 = g_rec[e + 3];
        float4 v0 = __ldg(&h4[(size_t)r0.x * 16 + p]);
        float4 v1 = __ldg(&h4[(size_t)r1.x * 16 + p]);
        float4 v2 = __ldg(&h4[(size_t)r2.x * 16 + p]);
        float4 v3 = __ldg(&h4[(size_t)r3.x * 16 + p]);
        float w0 = __uint_as_float(r0.y), w1 = __uint_as_float(r1.y);
        float w2 = __uint_as_float(r2.y), w3 = __uint_as_float(r3.y);
        acc.x = fmaf(v0.x, w0, acc.x); acc.y = fmaf(v0.y, w0, acc.y);
        acc.z = fmaf(v0.z, w0, acc.z); acc.w = fmaf(v0.w, w0, acc.w);
        acc.x = fmaf(v1.x, w1, acc.x); acc.y = fmaf(v1.y, w1, acc.y);
        acc.z = fmaf(v1.z, w1, acc.z); acc.w = fmaf(v1.w, w1, acc.w);
        acc.x = fmaf(v2.x, w2, acc.x); acc.y = fmaf(v2.y, w2, acc.y);
        acc.z = fmaf(v2.z, w2, acc.z); acc.w = fmaf(v2.w, w2, acc.w);
        acc.x = fmaf(v3.x, w3, acc.x); acc.y = fmaf(v3.y, w3, acc.y);
        acc.z = fmaf(v3.z, w3, acc.z); acc.w = fmaf(v3.w, w3, acc.w);
    }
    for (; e < end; e++) {
        uint2 r = g_rec[e];
        float4 v = __ldg(&h4[(size_t)r.x * 16 + p]);
        float w = __uint_as_float(r.y);
        acc.x = fmaf(v.x, w, acc.x); acc.y = fmaf(v.y, w, acc.y);
        acc.z = fmaf(v.z, w, acc.z); acc.w = fmaf(v.w, w, acc.w);
    }
    g_hnew4[node * 16 + p] = acc;
}

// ---------------------------------------------------------------------------
// prep — bf16 hi/lo weight image, GROUPED col order [r|z|i_n|h_n], + biases.
// col' = g*64 + j. i_n cols: x-part at k<64, zeros k>=64; h_n: zeros, h-part.
// ---------------------------------------------------------------------------
__global__ void prep_kernel(const float* __restrict__ Wih,
                            const float* __restrict__ Whh,
                            const float* __restrict__ bih,
                            const float* __restrict__ bhh) {
    int idx = blockIdx.x * blockDim.x + threadIdx.x;   // 256 cols' x 32 quads
    if (idx < 8192) {
        int colp = idx >> 5, q = idx & 31;             // q: 4-k quad, q<16 -> x half
        int g = colp >> 6, j = colp & 63;
        int kk = (q & 15) * 4;
        bool isX = (q < 16);
        float4 v = make_float4(0.f, 0.f, 0.f, 0.f);
        const float* srcRow = nullptr;
        if (g == 0)      srcRow = isX ? &Wih[j * 64]         : &Whh[j * 64];
        else if (g == 1) srcRow = isX ? &Wih[(64 + j) * 64]  : &Whh[(64 + j) * 64];
        else if (g == 2) srcRow = isX ? &Wih[(128 + j) * 64] : nullptr;
        else             srcRow = isX ? nullptr              : &Whh[(128 + j) * 64];
        if (srcRow) v = *(const float4*)(srcRow + kk);

        uint32_t h01 = cvtbf2(v.y, v.x), h23 = cvtbf2(v.w, v.z);
        uint32_t l01 = cvtbf2(v.y - bfhi_f(h01), v.x - bflo_f(h01));
        uint32_t l23 = cvtbf2(v.w - bfhi_f(h23), v.z - bflo_f(h23));
        uint32_t off = (uint32_t)colp * STRIDE_A + ((q >> 1) << 4) + ((q & 1) << 3);
        *(uint2*)(g_Bimg + off)          = make_uint2(h01, h23);
        *(uint2*)(g_Bimg + off + B_HALF) = make_uint2(l01, l23);
    }
    if (idx < 64) {
        g_biasf[idx]       = bih[idx] + bhh[idx];
        g_biasf[64 + idx]  = bih[64 + idx] + bhh[64 + idx];
        g_biasf[128 + idx] = bih[128 + idx];
        g_biasf[192 + idx] = bhh[128 + idx];
    }
}

// ---------------------------------------------------------------------------
// GEMM + GRU epilogue: warp-independent 16-row tiles; grouped-gate B layout.
// Frags: r = 0..7, z = 8..15, i_n = 16..23 (k-steps 0..3 only),
//        h_n = 24..31 (k-steps 4..7 only) -> 25% fewer MMAs, no shuffles.
// ---------------------------------------------------------------------------
#define GEMM_STEP(S, NB, GRP)                                                  \
    do {                                                                       \
        uint32_t b0, b1, b2, b3;                                               \
        LDSM4(b0, b1, b2, b3,                                                  \
              bbase_##GRP + (uint32_t)(NB) * (16 * STRIDE_A) + (uint32_t)(S) * 32); \
        float* c0 = &acc[((NB) * 2) * 4];                                      \
        float* c1 = &acc[((NB) * 2 + 1) * 4];                                  \
        MMA16816(c0, ah0, ah1, ah2, ah3, b0, b1);                              \
        MMA16816(c1, ah0, ah1, ah2, ah3, b2, b3);                              \
        if (GRP == 0) {                                                        \
            MMA16816(c0, al0, al1, al2, al3, b0, b1);                          \
            MMA16816(c1, al0, al1, al2, al3, b2, b3);                          \
        }                                                                      \
    } while (0)

__global__ void __launch_bounds__(256, 1)
gemm_gru_kernel(const float4* __restrict__ h4, float* __restrict__ out,
                int Nn, int n_tiles16) {
    extern __shared__ __align__(16) char smem[];
    const uint32_t sb = smem_u32(smem);
    const int tid = threadIdx.x;
    const int w = tid >> 5, l = tid & 31;
    const int r0q = l >> 2, tg = l & 3;

    // --- B image + bias -> SMEM ---
    {
        const uint4* srcB = (const uint4*)g_Bimg;
        uint4* dstB = (uint4*)(smem + SM_B);
        for (int i = tid; i < (2 * B_HALF) / 16; i += 256) dstB[i] = srcB[i];
        ((float*)smem)[tid] = g_biasf[tid];
    }
    __syncthreads();

    const int warpA_off = SM_A + w * A_WARP;
    const int sel = l >> 3;
    const uint32_t a_base = sb + (uint32_t)warpA_off +
        (uint32_t)((((sel & 1) << 3) + (l & 7)) * STRIDE_A + ((sel >> 1) << 4));
    const uint32_t b_base = sb + SM_B +
        (uint32_t)((((sel >> 1) << 3) + (l & 7)) * STRIDE_A + ((sel & 1) << 4));

    for (int tw = blockIdx.x * 8 + w; tw < n_tiles16; tw += gridDim.x * 8) {
        const int m0 = tw << 4;

        // --- A tile (16 rows, warp-private): f32 -> bf16 hi/lo split ---
#pragma unroll
        for (int it = 0; it < 16; it++) {
            int node = m0 + it;
            int kq = l;
            float4 v = make_float4(0.f, 0.f, 0.f, 0.f);
            if (node < Nn)
                v = (kq < 16) ? g_hnew4[node * 16 + kq]
                              : __ldg(&h4[node * 16 + (kq - 16)]);
            uint32_t h01 = cvtbf2(v.y, v.x), h23 = cvtbf2(v.w, v.z);
            uint32_t l01 = cvtbf2(v.y - bfhi_f(h01), v.x - bflo_f(h01));
            uint32_t l23 = cvtbf2(v.w - bfhi_f(h23), v.z - bflo_f(h23));
            uint32_t off = (uint32_t)warpA_off + (uint32_t)it * STRIDE_A +
                           ((uint32_t)(kq >> 1) << 4) + ((uint32_t)(kq & 1) << 3);
            *(uint2*)(smem + off)            = make_uint2(h01, h23);
            *(uint2*)(smem + off + A_HALF_W) = make_uint2(l01, l23);
        }
        __syncwarp();

        float acc[128];
#pragma unroll
        for (int i = 0; i < 128; i++) acc[i] = 0.f;

        // ---- group 0: (Ahi + Alo) x Bhi ----
        {
            const uint32_t bbase_0 = b_base;
#pragma unroll 1
            for (int s = 0; s < 4; s++) {          // low-k: r,z + i_n (nb 8..11)
                uint32_t ah0, ah1, ah2, ah3, al0, al1, al2, al3;
                LDSM4(ah0, ah1, ah2, ah3, a_base + (uint32_t)s * 32);
                LDSM4(al0, al1, al2, al3, a_base + A_HALF_W + (uint32_t)s * 32);
#pragma unroll
                for (int q = 0; q < 12; q++) GEMM_STEP(s, q, 0);
            }
#pragma unroll 1
            for (int s = 4; s < 8; s++) {          // high-k: r,z + h_n (nb 12..15)
                uint32_t ah0, ah1, ah2, ah3, al0, al1, al2, al3;
                LDSM4(ah0, ah1, ah2, ah3, a_base + (uint32_t)s * 32);
                LDSM4(al0, al1, al2, al3, a_base + A_HALF_W + (uint32_t)s * 32);
#pragma unroll
                for (int q = 0; q < 12; q++) { int nb = (q < 8) ? q : q + 4; GEMM_STEP(s, nb, 0); }
            }
        }
        // ---- group 1: Ahi x Blo ----
        {
            const uint32_t bbase_1 = b_base + B_HALF;
#pragma unroll 1
            for (int s = 0; s < 4; s++) {
                uint32_t ah0, ah1, ah2, ah3;
                uint32_t al0 = 0, al1 = 0, al2 = 0, al3 = 0; (void)al0;
                LDSM4(ah0, ah1, ah2, ah3, a_base + (uint32_t)s * 32);
#pragma unroll
                for (int q = 0; q < 12; q++) GEMM_STEP(s, q, 1);
            }
#pragma unroll 1
            for (int s = 4; s < 8; s++) {
                uint32_t ah0, ah1, ah2, ah3;
                uint32_t al0 = 0, al1 = 0, al2 = 0, al3 = 0; (void)al0;
                LDSM4(ah0, ah1, ah2, ah3, a_base + (uint32_t)s * 32);
#pragma unroll
                for (int q = 0; q < 12; q++) { int nb = (q < 8) ? q : q + 4; GEMM_STEP(s, nb, 1); }
            }
        }

        // --- Epilogue phase 1: gate math (no shuffles); stash into r-frag slots ---
#pragma unroll
        for (int rs = 0; rs < 2; rs++) {
            const int node_local = r0q + rs * 8;
#pragma unroll
            for (int fn = 0; fn < 8; fn++) {
                const uint32_t bj = (uint32_t)((fn * 8 + tg * 2) * 4);
                float2 br = *(const float2*)(smem + SM_BIAS + bj);
                float2 bz = *(const float2*)(smem + SM_BIAS + 256 + bj);
                float2 bi = *(const float2*)(smem + SM_BIAS + 512 + bj);
                float2 bh = *(const float2*)(smem + SM_BIAS + 768 + bj);
#pragma unroll
                for (int b = 0; b < 2; b++) {
                    int j = fn * 8 + tg * 2 + b;
                    float rp = acc[fn * 4 + 2 * rs + b];
                    float zp = acc[(fn + 8) * 4 + 2 * rs + b];
                    float ip = acc[(fn + 16) * 4 + 2 * rs + b];
                    float hp = acc[(fn + 24) * 4 + 2 * rs + b];
                    float rr = sigmoidf_fast(rp + (b ? br.y : br.x));
                    float zz = sigmoidf_fast(zp + (b ? bz.y : bz.x));
                    float nn = tanhf_fast(ip + (b ? bi.y : bi.x) +
                                          rr * (hp + (b ? bh.y : bh.x)));
                    int kcol = 64 + j;
                    uint32_t hoff = (uint32_t)warpA_off +
                                    (uint32_t)node_local * STRIDE_A +
                                    ((uint32_t)(kcol >> 3) << 4) +
                                    ((uint32_t)(kcol & 7) << 1);
                    uint32_t hib = *(const unsigned short*)(smem + hoff);
                    uint32_t lob = *(const unsigned short*)(smem + hoff + A_HALF_W);
                    float hv = __uint_as_float(hib << 16) + __uint_as_float(lob << 16);
                    acc[fn * 4 + 2 * rs + b] = (1.f - zz) * nn + zz * hv;
                }
            }
        }
        __syncwarp();

        // --- Epilogue phase 2: stage float2 into warp-private SMEM (XOR sw) ---
#pragma unroll
        for (int rs = 0; rs < 2; rs++) {
            const int nl = r0q + rs * 8;
            const uint32_t sw = ((uint32_t)(nl & 7)) << 2;
#pragma unroll
            for (int fn = 0; fn < 8; fn++) {
                uint32_t u = (uint32_t)(fn * 4 + tg);
                uint32_t sa = (uint32_t)warpA_off + (uint32_t)nl * 256 +
                              ((u ^ sw) << 3);
                *(float2*)(smem + sa) =
                    make_float2(acc[fn * 4 + 2 * rs], acc[fn * 4 + 2 * rs + 1]);
            }
        }
        __syncwarp();

        // --- Epilogue phase 3: coalesced 16B stores ---
#pragma unroll
        for (int it = 0; it < 8; it++) {
            int idx = it * 32 + l;
            int nl = idx >> 4, c16 = idx & 15;
            uint32_t ra = (uint32_t)warpA_off + (uint32_t)nl * 256 +
                          ((uint32_t)(c16 ^ ((nl & 7) << 1)) << 4);
            float4 v = *(const float4*)(smem + ra);
            int node = m0 + nl;
            if (node < Nn) *(float4*)(out + (size_t)node * 64 + c16 * 4) = v;
        }
        __syncwarp();
    }
}

// ---------------------------------------------------------------------------
// Launch
// ---------------------------------------------------------------------------
extern "C" void kernel_launch(void* const* d_in, const int* in_sizes, int n_in,
                              void* d_out, int out_size) {
    const float* h   = (const float*)d_in[0];
    const float* ew  = (const float*)d_in[1];
    const float* Wih = (const float*)d_in[2];
    const float* Whh = (const float*)d_in[3];
    const float* bih = (const float*)d_in[4];
    const float* bhh = (const float*)d_in[5];
    const void* srcp = d_in[6];
    const void* dstp = d_in[7];
    float* out       = (float*)d_out;

    int E  = in_sizes[1];
    int Nn = in_sizes[0] / D;
    int n_tiles16 = (Nn + 15) / 16;
    int eblocks = (E + 255) / 256;
    int nb = (Nn + 1023) / 1024;

    zcnt_kernel<<<(Nn + 255) / 256, 256>>>((const unsigned long long*)srcp,
                                           (const unsigned long long*)dstp, Nn);
    hist_kernel<<<eblocks, 256>>>(dstp, E);
    scanA_kernel<<<nb, 1024>>>(Nn);
    scanB_kernel<<<1, 128>>>(nb);
    scanC_kernel<<<(Nn + 255) / 256, 256>>>(Nn, E);
    reorder_kernel<<<eblocks, 256>>>(srcp, dstp, ew, E);

    prep_kernel<<<32, 256>>>(Wih, Whh, bih, bhh);

    accum_kernel<<<(Nn * 16 + 255) / 256, 256>>>((const float4*)h, Nn);

    cudaFuncSetAttribute(gemm_gru_kernel,
                         cudaFuncAttributeMaxDynamicSharedMemorySize, SM_TOT);
    gemm_gru_kernel<<<148, 256, SM_TOT>>>((const float4*)h, out, Nn, n_tiles16);
}